// round 3
// baseline (speedup 1.0000x reference)
#include <cuda_runtime.h>
#include <math_constants.h>
#include <cstdint>

#define NLEV 1024
#define KP1  9
#define NB   8192
#define MAIN_THREADS 512

// Scratch (allocation-free: __device__ globals)
__device__ float g_mid[NLEV];     // midpoints m[0..1022], m[1023] = +INF sentinel
__device__ float g_lut[NLEV];     // per-nidx output value
__device__ float g_table[NB];     // per-bucket: value, or NaN|base sentinel
__device__ float g_scale, g_ofs;  // bucket affine map

// Monotone bucket map — MUST be bit-identical wherever used.
__device__ __forceinline__ int bucket_of(float x, float scale, float ofs) {
    float v = __fmaf_rn(x, scale, ofs);
    v = fminf(fmaxf(v, 0.0f), (float)(NB - 1));
    return (int)v;   // trunc == floor for v >= 0
}

// ---------------------------------------------------------------------------
// Setup A: LUT per level + midpoints + bucket affine params. 1 block, 1024 thr.
// Reference loop uses h[:,0] for t=1 and h[:,t] for t=2..8 (column 1 unused).
// ---------------------------------------------------------------------------
__global__ void setup_lut_mid(const float* __restrict__ h,
                              const float* __restrict__ d,
                              const float* __restrict__ T,
                              const float* __restrict__ b) {
    int i = threadIdx.x;                 // 0..1023
    float h0 = h[i * KP1];
    float acc = -b[0];
    acc += (h0 - T[1] >= 0.0f) ? d[1] : 0.0f;
#pragma unroll
    for (int t = 2; t <= 8; t++)
        acc += (h[i * KP1 + t] - T[t] >= 0.0f) ? d[t] : 0.0f;
    g_lut[i] = acc;

    float m;
    if (i < NLEV - 1) m = 0.5f * (h0 + h[(i + 1) * KP1]);
    else              m = CUDART_INF_F;  // sentinel stops slow-path scan
    g_mid[i] = m;

    __shared__ float s_lo, s_hi;
    if (i == 0)        s_lo = m;
    if (i == NLEV - 2) s_hi = m;
    __syncthreads();
    if (i == 0) {
        float scale = (float)NB / (s_hi - s_lo);
        g_scale = scale;
        g_ofs   = -s_lo * scale;
    }
}

// ---------------------------------------------------------------------------
// Setup B: build bucket table. 8 blocks x 1024 threads = 8192 buckets.
// base[b] = #{midpoints with bucket < b} via branch-free binary search.
// Bucket ambiguous iff some midpoint maps to bucket b.
// ---------------------------------------------------------------------------
__global__ void setup_table() {
    __shared__ float s_m[NLEV];
    int t = threadIdx.x;
    s_m[t] = g_mid[t];
    __syncthreads();

    int bkt = blockIdx.x * 1024 + t;     // 0..8191
    float scale = g_scale, ofs = g_ofs;

    int pos = 0;
#pragma unroll
    for (int step = 512; step >= 1; step >>= 1) {
        float mv = s_m[pos + step - 1];
        if (bucket_of(mv, scale, ofs) < bkt) pos += step;
    }
    // pos == count of midpoints whose bucket < bkt  (sentinel never counts)
    float val;
    if (pos < NLEV - 1 && bucket_of(s_m[pos], scale, ofs) == bkt)
        val = __uint_as_float(0x7FC00000u | (unsigned)pos);   // NaN | base
    else
        val = g_lut[pos];
    g_table[bkt] = val;
}

// ---------------------------------------------------------------------------
// Main kernel: 1 smem lookup per element (fast path), short scan otherwise.
// ---------------------------------------------------------------------------
__device__ __forceinline__ float eval_one(float xv, float scale, float ofs,
                                          const float* s_table,
                                          const float* s_mid,
                                          const float* s_lut) {
    int b = bucket_of(xv, scale, ofs);
    float r = s_table[b];
    unsigned u = __float_as_uint(r);
    if ((u & 0x7FC00000u) == 0x7FC00000u) {         // sentinel (fast-math safe)
        int nidx = (int)(u & 1023u);
        while (s_mid[nidx] <= xv) nidx++;           // stops at +INF sentinel
        r = s_lut[nidx];
    }
    return r;
}

__global__ void __launch_bounds__(MAIN_THREADS)
ps_main(const float4* __restrict__ x, float4* __restrict__ out, int n4,
        const float* __restrict__ x_tail, float* __restrict__ out_tail, int ntail) {
    __shared__ float s_table[NB];
    __shared__ float s_mid[NLEV];
    __shared__ float s_lut[NLEV];
    int tid = threadIdx.x;
    for (int j = tid; j < NB; j += MAIN_THREADS) s_table[j] = g_table[j];
    for (int j = tid; j < NLEV; j += MAIN_THREADS) { s_mid[j] = g_mid[j]; s_lut[j] = g_lut[j]; }
    float scale = g_scale, ofs = g_ofs;
    __syncthreads();

    int stride = gridDim.x * MAIN_THREADS;
    for (int i = blockIdx.x * MAIN_THREADS + tid; i < n4; i += stride) {
        float4 v = x[i];
        float4 o;
        o.x = eval_one(v.x, scale, ofs, s_table, s_mid, s_lut);
        o.y = eval_one(v.y, scale, ofs, s_table, s_mid, s_lut);
        o.z = eval_one(v.z, scale, ofs, s_table, s_mid, s_lut);
        o.w = eval_one(v.w, scale, ofs, s_table, s_mid, s_lut);
        out[i] = o;
    }
    // tail (n not divisible by 4) — at most 3 elements
    if (blockIdx.x == 0 && tid < ntail)
        out_tail[tid] = eval_one(x_tail[tid], scale, ofs, s_table, s_mid, s_lut);
}

// ---------------------------------------------------------------------------
extern "C" void kernel_launch(void* const* d_in, const int* in_sizes, int n_in,
                              void* d_out, int out_size) {
    const float* x = (const float*)d_in[0];
    const float* h = (const float*)d_in[1];
    const float* d = (const float*)d_in[2];
    const float* T = (const float*)d_in[3];
    const float* b = (const float*)d_in[4];
    float* out = (float*)d_out;

    int n  = in_sizes[0];
    int n4 = n >> 2;
    int ntail = n - (n4 << 2);

    setup_lut_mid<<<1, NLEV>>>(h, d, T, b);
    setup_table<<<NB / 1024, 1024>>>();

    int nblocks = 152 * 4;   // grid-stride; ~4 blocks/SM (40KB smem each)
    ps_main<<<nblocks, MAIN_THREADS>>>((const float4*)x, (float4*)out, n4,
                                       x + (n4 << 2), out + (n4 << 2), ntail);
}